// round 4
// baseline (speedup 1.0000x reference)
#include <cuda_runtime.h>
#include <cstdint>

// T=4 tables, E=1e6 rows, D=128 dim, B=8192 bags, L=32 per bag.
// indices: int32 [T,B,L] (1,048,576 el)   weights: f32 [T,E,D] (512,000,000 el)
// out: f32 [B, T*D]
//
// Warp per bag; lane owns float4 d-slice; rows broadcast via shfl.
// Explicit 8-wide load batching + 4 rotating accumulators to raise per-warp
// MLP (prev version: regs=32 capped in-flight gathers; DRAM stuck at 78.6%).

namespace {
constexpr int T = 4;
constexpr long long E = 1000000;
constexpr int D = 128;
constexpr int B = 8192;
constexpr int L = 32;
constexpr int D4 = D / 4;
constexpr int WARPS_PER_BLOCK = 8;
constexpr int THREADS = WARPS_PER_BLOCK * 32;
constexpr int NUM_BAGS = T * B;
constexpr long long IDX_ELEMS = (long long)T * B * L;
constexpr int BATCH = 8;
}

__global__ __launch_bounds__(THREADS, 3)
void embedding_bag_sum_kernel(const int* __restrict__ indices,
                              const float4* __restrict__ weights,
                              float4* __restrict__ out)
{
    const int warp_in_block = threadIdx.x >> 5;
    const int lane = threadIdx.x & 31;
    const int bag = blockIdx.x * WARPS_PER_BLOCK + warp_in_block;

    const int t = bag >> 13;          // bag / B
    const int b = bag & (B - 1);

    const int my_idx = __ldg(indices + (size_t)bag * L + lane);
    const float4* wt = weights + (size_t)t * (size_t)E * D4;

    float4 acc0 = make_float4(0.f, 0.f, 0.f, 0.f);
    float4 acc1 = make_float4(0.f, 0.f, 0.f, 0.f);
    float4 acc2 = make_float4(0.f, 0.f, 0.f, 0.f);
    float4 acc3 = make_float4(0.f, 0.f, 0.f, 0.f);

    #pragma unroll
    for (int base = 0; base < L; base += BATCH) {
        float4 v[BATCH];
        // Issue BATCH independent gathers before touching any of them.
        #pragma unroll
        for (int j = 0; j < BATCH; ++j) {
            const int row = __shfl_sync(0xffffffffu, my_idx, base + j);
            v[j] = __ldg(wt + (size_t)row * D4 + lane);
        }
        #pragma unroll
        for (int j = 0; j < BATCH; j += 4) {
            acc0.x += v[j].x;   acc0.y += v[j].y;   acc0.z += v[j].z;   acc0.w += v[j].w;
            acc1.x += v[j+1].x; acc1.y += v[j+1].y; acc1.z += v[j+1].z; acc1.w += v[j+1].w;
            acc2.x += v[j+2].x; acc2.y += v[j+2].y; acc2.z += v[j+2].z; acc2.w += v[j+2].w;
            acc3.x += v[j+3].x; acc3.y += v[j+3].y; acc3.z += v[j+3].z; acc3.w += v[j+3].w;
        }
    }

    float4 acc;
    acc.x = (acc0.x + acc1.x) + (acc2.x + acc3.x);
    acc.y = (acc0.y + acc1.y) + (acc2.y + acc3.y);
    acc.z = (acc0.z + acc1.z) + (acc2.z + acc3.z);
    acc.w = (acc0.w + acc1.w) + (acc2.w + acc3.w);

    out[((size_t)b * T + t) * D4 + lane] = acc;
}

extern "C" void kernel_launch(void* const* d_in, const int* in_sizes, int n_in,
                              void* d_out, int out_size)
{
    const int*    indices = nullptr;
    const float4* weights = nullptr;
    for (int i = 0; i < n_in; ++i) {
        if ((long long)in_sizes[i] == IDX_ELEMS)
            indices = (const int*)d_in[i];
        else
            weights = (const float4*)d_in[i];
    }
    float4* out = (float4*)d_out;

    const int blocks = NUM_BAGS / WARPS_PER_BLOCK;  // 4096
    embedding_bag_sum_kernel<<<blocks, THREADS>>>(indices, weights, out);
}